// round 1
// baseline (speedup 1.0000x reference)
#include <cuda_runtime.h>
#include <math.h>

// Problem constants (fixed by setup_inputs)
#define Bdim 4
#define Sdim 1024
#define Ddim 256
#define Hn   6
#define Hd   64
#define HF   384          // Hn*Hd
#define En   3
#define SENT_END 988      // S - sect - doc
#define SECT_END 1020     // S - doc
#define MAXDEG 256
#define BS  (Bdim*Sdim)   // 4096
#define BSD (BS*Ddim)     // 1048576

// ----------------------------- device scratch -----------------------------
__device__ __align__(128) int   g_nbr[BS*MAXDEG];      // CSR neighbor lists (sorted by j)
__device__ __align__(128) int   g_cnt[BS*3];           // cumulative counts: <988, <1020, total
__device__ __align__(128) float g_mask[En*BS];         // routing mask per expert
__device__ __align__(128) float g_W1t[4*Ddim*HF];      // W1 transposed to [D, H*Hd] (main + 3 dep)
__device__ __align__(128) float g_h [BS*HF];
__device__ __align__(128) float g_h1[BS*HF];
__device__ __align__(128) float g_h2[BS*Ddim];
__device__ __align__(128) float g_es[Bdim*Hn*Sdim];
__device__ __align__(128) float g_ed[Bdim*Hn*Sdim];
__device__ __align__(128) float g_s2[BS];
__device__ __align__(128) float g_d2[BS];
__device__ __align__(128) float g_main[BSD];
__device__ __align__(128) float g_dep[BSD];
__device__ __align__(128) float g_blend[BSD];
__device__ __align__(128) float g_meanh[Bdim*HF];
__device__ __align__(128) float g_meanh2[Bdim*Ddim];
__device__ __align__(128) float g_part[1024];

// ----------------------------- kernels -----------------------------

__global__ void k_zero_dep() {
    g_dep[(size_t)blockIdx.x*256 + threadIdx.x] = 0.f;
}

// one warp per row: compact adjacency row into CSR (preserves ascending j order)
__global__ void k_build_csr(const float* __restrict__ adj) {
    int warp = (blockIdx.x*blockDim.x + threadIdx.x) >> 5;
    int lane = threadIdx.x & 31;
    if (warp >= BS) return;
    const float* row = adj + (size_t)warp * Sdim;
    int cnt = 0, c0 = 0, c1 = 0;
    for (int c = 0; c < Sdim; c += 32) {
        int j = c + lane;
        float v = row[j];
        unsigned m = __ballot_sync(0xffffffffu, v > 0.f);
        if (v > 0.f) {
            int pos = cnt + __popc(m & ((1u << lane) - 1u));
            if (pos < MAXDEG) g_nbr[warp*MAXDEG + pos] = j;
        }
        unsigned msent = __ballot_sync(0xffffffffu, j < SENT_END);
        unsigned msect = __ballot_sync(0xffffffffu, j < SECT_END);
        cnt += __popc(m);
        c0  += __popc(m & msent);
        c1  += __popc(m & msect);
    }
    if (lane == 0) {
        g_cnt[warp*3+0] = c0; g_cnt[warp*3+1] = c1; g_cnt[warp*3+2] = cnt;
    }
}

// one warp per node: router logits; top-2 of 3 == exclude argmin (ties -> larger idx)
__global__ void k_router(const float* __restrict__ x, const float* __restrict__ rw) {
    int warp = (blockIdx.x*blockDim.x + threadIdx.x) >> 5;
    int lane = threadIdx.x & 31;
    if (warp >= BS) return;
    const float* xp = x + (size_t)warp * Ddim;
    float l0 = 0.f, l1 = 0.f, l2 = 0.f;
    for (int d = lane; d < Ddim; d += 32) {
        float v = xp[d];
        l0 += v * rw[d*3+0];
        l1 += v * rw[d*3+1];
        l2 += v * rw[d*3+2];
    }
    for (int o = 16; o; o >>= 1) {
        l0 += __shfl_xor_sync(0xffffffffu, l0, o);
        l1 += __shfl_xor_sync(0xffffffffu, l1, o);
        l2 += __shfl_xor_sync(0xffffffffu, l2, o);
    }
    if (lane == 0) {
        int excl = 0; float mn = l0;
        if (l1 <= mn) { mn = l1; excl = 1; }
        if (l2 <= mn) { mn = l2; excl = 2; }
        g_mask[0*BS + warp] = (excl == 0) ? 0.f : 1.f;
        g_mask[1*BS + warp] = (excl == 1) ? 0.f : 1.f;
        g_mask[2*BS + warp] = (excl == 2) ? 0.f : 1.f;
    }
}

// transpose W1 [H,D,Hd] -> [D, H*Hd], for main (slot 0) and 3 deputies
__global__ void k_transW1(const float* __restrict__ mW1, const float* __restrict__ dW1) {
    int i = blockIdx.x*blockDim.x + threadIdx.x;
    if (i >= 4*Ddim*HF) return;
    int e = i / (Ddim*HF);
    int r = i - e*(Ddim*HF);
    int f = r / HF;
    int ho = r - f*HF;
    int hh = ho >> 6, o = ho & 63;
    const float* src = (e == 0) ? mW1 : (dW1 + (size_t)(e-1)*Hn*Ddim*Hd);
    g_W1t[i] = src[(hh*Ddim + f)*Hd + o];
}

// generic tiled SGEMM: C[M,N] = A[M,K] @ B[K,N], optional per-row output mask
// M % 128 == 0, N % 64 == 0, K % 16 == 0
__global__ void __launch_bounds__(256) k_sgemm(
    const float* __restrict__ A, const float* __restrict__ B, float* __restrict__ C,
    int M, int N, int K, const float* __restrict__ rowmask)
{
    __shared__ __align__(16) float As[16][128];
    __shared__ __align__(16) float Bs[16][64];
    int tid = threadIdx.x;
    int tx = tid & 15;   // N direction (x4)
    int ty = tid >> 4;   // M direction (x8)
    int bx = blockIdx.x; // N tile
    int by = blockIdx.y; // M tile
    const float* Ab = A + (size_t)by*128*K;
    const float* Bb = B + bx*64;
    float acc[8][4];
    #pragma unroll
    for (int i = 0; i < 8; i++)
        #pragma unroll
        for (int j = 0; j < 4; j++) acc[i][j] = 0.f;

    for (int k0 = 0; k0 < K; k0 += 16) {
        #pragma unroll
        for (int l = 0; l < 2; l++) {
            int q  = tid + l*256;          // 512 float4 loads cover 128x16
            int r  = q >> 2;
            int c4 = q & 3;
            float4 v = *(const float4*)(Ab + (size_t)r*K + k0 + c4*4);
            As[c4*4+0][r] = v.x; As[c4*4+1][r] = v.y;
            As[c4*4+2][r] = v.z; As[c4*4+3][r] = v.w;
        }
        {
            int r  = tid >> 4;             // 0..15
            int c4 = tid & 15;             // 16 float4 per row
            float4 v = *(const float4*)(Bb + (size_t)(k0 + r)*N + c4*4);
            *(float4*)&Bs[r][c4*4] = v;
        }
        __syncthreads();
        #pragma unroll
        for (int k = 0; k < 16; k++) {
            float4 a0 = *(const float4*)&As[k][ty*8];
            float4 a1 = *(const float4*)&As[k][ty*8+4];
            float4 b0 = *(const float4*)&Bs[k][tx*4];
            float a[8] = {a0.x,a0.y,a0.z,a0.w,a1.x,a1.y,a1.z,a1.w};
            float bb[4] = {b0.x,b0.y,b0.z,b0.w};
            #pragma unroll
            for (int i = 0; i < 8; i++)
                #pragma unroll
                for (int j = 0; j < 4; j++) acc[i][j] += a[i]*bb[j];
        }
        __syncthreads();
    }
    #pragma unroll
    for (int i = 0; i < 8; i++) {
        int row = by*128 + ty*8 + i;
        float mv = rowmask ? rowmask[row] : 1.f;
        float* cp = C + (size_t)row*N + bx*64 + tx*4;
        cp[0] = acc[i][0]*mv; cp[1] = acc[i][1]*mv;
        cp[2] = acc[i][2]*mv; cp[3] = acc[i][3]*mv;
    }
}

// per-(b,h,s) attention source/dest projections for layer 1
__global__ void k_esed(const float* __restrict__ a1s, const float* __restrict__ a1d) {
    int idx = blockIdx.x*blockDim.x + threadIdx.x;
    if (idx >= Bdim*Hn*Sdim) return;
    int s  = idx & (Sdim-1);
    int bh = idx >> 10;
    int hh = bh % Hn;
    int b  = bh / Hn;
    const float* hp = g_h + ((size_t)(b*Sdim + s))*HF + hh*Hd;
    const float* as = a1s + hh*Hd;
    const float* ad = a1d + hh*Hd;
    float x = 0.f, y = 0.f;
    #pragma unroll 8
    for (int o = 0; o < Hd; o++) { float v = hp[o]; x += v*as[o]; y += v*ad[o]; }
    g_es[idx] = x; g_ed[idx] = y;
}

// layer-1 sparse attention + ELU.  expert: -1 main (full CSR), 0/1/2 deputy (segment)
__global__ void __launch_bounds__(384) k_att1(int expert) {
    int row = blockIdx.x;
    int b = row >> 10, s = row & 1023;
    __shared__ float sc[Hn][MAXDEG];
    __shared__ int   snbr[MAXDEG];
    __shared__ float sden[Hn];
    const int* c = g_cnt + row*3;
    int lo = 0, hi;
    if      (expert < 0)  hi = c[2];
    else if (expert == 0) hi = c[0];
    else if (expert == 1) { lo = c[0]; hi = c[1]; }
    else                  { lo = c[1]; hi = c[2]; }
    int deg = hi - lo;
    int tid = threadIdx.x;
    if (deg == 0) {  // all scores -1e9 -> uniform attention over all S -> column mean
        for (int o = tid; o < HF; o += 384) {
            float v = g_meanh[b*HF + o];
            g_h1[(size_t)row*HF + o] = (v > 0.f) ? v : expm1f(v);
        }
        return;
    }
    for (int j = tid; j < deg; j += 384) snbr[j] = g_nbr[row*MAXDEG + lo + j];
    __syncthreads();
    for (int idx = tid; idx < Hn*deg; idx += 384) {
        int hh = idx / deg;
        int j  = idx - hh*deg;
        float v = g_es[(b*Hn+hh)*Sdim + s] + g_ed[(b*Hn+hh)*Sdim + snbr[j]];
        sc[hh][j] = (v > 0.f) ? v : 0.2f*v;
    }
    __syncthreads();
    int warp = tid >> 5, lane = tid & 31;
    if (warp < Hn) {
        float m = -1e30f;
        for (int j = lane; j < deg; j += 32) m = fmaxf(m, sc[warp][j]);
        for (int o = 16; o; o >>= 1) m = fmaxf(m, __shfl_xor_sync(0xffffffffu, m, o));
        float su = 0.f;
        for (int j = lane; j < deg; j += 32) { float e = expf(sc[warp][j] - m); sc[warp][j] = e; su += e; }
        for (int o = 16; o; o >>= 1) su += __shfl_xor_sync(0xffffffffu, su, o);
        if (lane == 0) sden[warp] = su;
    }
    __syncthreads();
    int hh = tid >> 6, o = tid & 63;
    const float* hb = g_h + (size_t)(b*Sdim)*HF + hh*Hd + o;
    float acc0 = 0.f, acc1 = 0.f;
    int j = 0;
    for (; j + 1 < deg; j += 2) {
        acc0 += sc[hh][j]   * hb[(size_t)snbr[j]*HF];
        acc1 += sc[hh][j+1] * hb[(size_t)snbr[j+1]*HF];
    }
    if (j < deg) acc0 += sc[hh][j] * hb[(size_t)snbr[j]*HF];
    float v = (acc0 + acc1) / sden[hh];
    g_h1[(size_t)row*HF + hh*Hd + o] = (v > 0.f) ? v : expm1f(v);
}

__global__ void k_s2d2(const float* __restrict__ a2s, const float* __restrict__ a2d) {
    int row = blockIdx.x*blockDim.x + threadIdx.x;
    if (row >= BS) return;
    const float* p = g_h2 + (size_t)row*Ddim;
    float x = 0.f, y = 0.f;
    #pragma unroll 8
    for (int d = 0; d < Ddim; d++) { float v = p[d]; x += v*a2s[d]; y += v*a2d[d]; }
    g_s2[row] = x; g_d2[row] = y;
}

// layer-2 sparse attention; main writes g_main, deputies accumulate masked rows into g_dep
__global__ void __launch_bounds__(256) k_att2(int expert) {
    int row = blockIdx.x;
    if (expert >= 0 && g_mask[expert*BS + row] == 0.f) return;  // output masked anyway
    int b = row >> 10;
    __shared__ float sc[MAXDEG];
    __shared__ int   snbr[MAXDEG];
    __shared__ float sden;
    const int* c = g_cnt + row*3;
    int lo = 0, hi;
    if      (expert < 0)  hi = c[2];
    else if (expert == 0) hi = c[0];
    else if (expert == 1) { lo = c[0]; hi = c[1]; }
    else                  { lo = c[1]; hi = c[2]; }
    int deg = hi - lo;
    int tid = threadIdx.x;
    if (deg == 0) {
        for (int o = tid; o < Ddim; o += 256) {
            float v = g_meanh2[b*Ddim + o];
            if (expert < 0) g_main[(size_t)row*Ddim + o] = v;
            else            g_dep [(size_t)row*Ddim + o] += v;
        }
        return;
    }
    for (int j = tid; j < deg; j += 256) snbr[j] = g_nbr[row*MAXDEG + lo + j];
    __syncthreads();
    float srcsc = g_s2[row];
    for (int j = tid; j < deg; j += 256) {
        float v = srcsc + g_d2[b*Sdim + snbr[j]];
        sc[j] = (v > 0.f) ? v : 0.2f*v;
    }
    __syncthreads();
    if (tid < 32) {
        float m = -1e30f;
        for (int j = tid; j < deg; j += 32) m = fmaxf(m, sc[j]);
        for (int o = 16; o; o >>= 1) m = fmaxf(m, __shfl_xor_sync(0xffffffffu, m, o));
        float su = 0.f;
        for (int j = tid; j < deg; j += 32) { float e = expf(sc[j] - m); sc[j] = e; su += e; }
        for (int o = 16; o; o >>= 1) su += __shfl_xor_sync(0xffffffffu, su, o);
        if (tid == 0) sden = su;
    }
    __syncthreads();
    const float* hb = g_h2 + (size_t)(b*Sdim)*Ddim + tid;
    float acc0 = 0.f, acc1 = 0.f;
    int j = 0;
    for (; j + 1 < deg; j += 2) {
        acc0 += sc[j]   * hb[(size_t)snbr[j]*Ddim];
        acc1 += sc[j+1] * hb[(size_t)snbr[j+1]*Ddim];
    }
    if (j < deg) acc0 += sc[j] * hb[(size_t)snbr[j]*Ddim];
    float v = (acc0 + acc1) / sden;
    if (expert < 0) g_main[(size_t)row*Ddim + tid] = v;
    else            g_dep [(size_t)row*Ddim + tid] += v;
}

// column means per batch (for zero-degree uniform-attention rows)
__global__ void k_colmean(const float* __restrict__ X, float* __restrict__ out, int cols) {
    int idx = blockIdx.x*blockDim.x + threadIdx.x;
    if (idx >= Bdim*cols) return;
    int b = idx / cols, cc = idx - b*cols;
    const float* p = X + (size_t)b*Sdim*cols + cc;
    float a0 = 0.f, a1 = 0.f, a2 = 0.f, a3 = 0.f;
    for (int r = 0; r < Sdim; r += 4) {
        a0 += p[(size_t)r*cols];
        a1 += p[(size_t)(r+1)*cols];
        a2 += p[(size_t)(r+2)*cols];
        a3 += p[(size_t)(r+3)*cols];
    }
    out[idx] = (a0 + a1 + a2 + a3) * (1.f/(float)Sdim);
}

// blend + final output + deterministic partial sums of blend weights
__global__ void __launch_bounds__(256) k_final(const float* __restrict__ bbias, float* __restrict__ out) {
    __shared__ float red[256];
    int t = threadIdx.x;
    int base = blockIdx.x*1024;
    float s = 0.f;
    #pragma unroll
    for (int l = 0; l < 4; l++) {
        int i = base + l*256 + t;
        int d = i & (Ddim-1);
        float w = 1.f / (1.f + expf(-(g_blend[i] + bbias[d])));
        out[i] = w*g_main[i] + (1.f - w)*g_dep[i];
        s += w;
    }
    red[t] = s; __syncthreads();
    for (int o = 128; o; o >>= 1) { if (t < o) red[t] += red[t+o]; __syncthreads(); }
    if (t == 0) g_part[blockIdx.x] = red[0];
}

__global__ void k_scalar(float* __restrict__ out) {
    __shared__ float red[256];
    int t = threadIdx.x;
    float s = 0.f;
    for (int i = t; i < 1024; i += 256) s += g_part[i];
    red[t] = s; __syncthreads();
    for (int o = 128; o; o >>= 1) { if (t < o) red[t] += red[t+o]; __syncthreads(); }
    if (t == 0) {
        float mc = red[0] / (float)BSD;
        out[BSD]     = fabsf(mc - 0.6f) * 0.01f;
        out[BSD + 1] = mc;
    }
}

// ----------------------------- host launcher -----------------------------
extern "C" void kernel_launch(void* const* d_in, const int* in_sizes, int n_in,
                              void* d_out, int out_size) {
    const float* feature = (const float*)d_in[0];
    const float* adj     = (const float*)d_in[1];
    const float* mW1     = (const float*)d_in[2];
    const float* ma1s    = (const float*)d_in[3];
    const float* ma1d    = (const float*)d_in[4];
    const float* mW2     = (const float*)d_in[5];
    const float* ma2s    = (const float*)d_in[6];
    const float* ma2d    = (const float*)d_in[7];
    const float* dW1     = (const float*)d_in[8];
    const float* da1s    = (const float*)d_in[9];
    const float* da1d    = (const float*)d_in[10];
    const float* dW2     = (const float*)d_in[11];
    const float* da2s    = (const float*)d_in[12];
    const float* da2d    = (const float*)d_in[13];
    const float* rW      = (const float*)d_in[14];
    const float* bW      = (const float*)d_in[15];
    const float* bbias   = (const float*)d_in[16];
    float* out = (float*)d_out;

    static float *p_h = nullptr, *p_h1, *p_h2, *p_W1t, *p_mask, *p_blend, *p_meanh, *p_meanh2;
    if (!p_h) {
        cudaGetSymbolAddress((void**)&p_h,      g_h);
        cudaGetSymbolAddress((void**)&p_h1,     g_h1);
        cudaGetSymbolAddress((void**)&p_h2,     g_h2);
        cudaGetSymbolAddress((void**)&p_W1t,    g_W1t);
        cudaGetSymbolAddress((void**)&p_mask,   g_mask);
        cudaGetSymbolAddress((void**)&p_blend,  g_blend);
        cudaGetSymbolAddress((void**)&p_meanh,  g_meanh);
        cudaGetSymbolAddress((void**)&p_meanh2, g_meanh2);
    }

    k_zero_dep<<<4096, 256>>>();
    k_router  <<<512, 256>>>(feature, rW);
    k_build_csr<<<512, 256>>>(adj);
    k_transW1 <<<1536, 256>>>(mW1, dW1);

    dim3 gemm1(HF/64, BS/128);    // N=384
    dim3 gemm2(Ddim/64, BS/128);  // N=256

    // ---- main expert ----
    k_sgemm<<<gemm1, 256>>>(feature, p_W1t, p_h, BS, HF, Ddim, nullptr);
    k_esed <<<96, 256>>>(ma1s, ma1d);
    k_att1 <<<4096, 384>>>(-1);
    k_sgemm<<<gemm2, 256>>>(p_h1, mW2, p_h2, BS, Ddim, HF, nullptr);
    k_s2d2 <<<16, 256>>>(ma2s, ma2d);
    k_att2 <<<4096, 256>>>(-1);

    // ---- deputy experts ----
    for (int e = 0; e < En; e++) {
        k_sgemm<<<gemm1, 256>>>(feature, p_W1t + (size_t)(1+e)*Ddim*HF, p_h, BS, HF, Ddim, p_mask + e*BS);
        k_esed <<<96, 256>>>(da1s + e*Hn*Hd, da1d + e*Hn*Hd);
        k_colmean<<<6, 256>>>(p_h, p_meanh, HF);
        k_att1 <<<4096, 384>>>(e);
        k_sgemm<<<gemm2, 256>>>(p_h1, dW2 + (size_t)e*HF*Ddim, p_h2, BS, Ddim, HF, nullptr);
        k_s2d2 <<<16, 256>>>(da2s + e*Ddim, da2d + e*Ddim);
        k_colmean<<<4, 256>>>(p_h2, p_meanh2, Ddim);
        k_att2 <<<4096, 256>>>(e);
    }

    // ---- blend + final ----
    k_sgemm<<<gemm2, 256>>>(feature, bW, p_blend, BS, Ddim, Ddim, nullptr);
    k_final<<<1024, 256>>>(bbias, out);
    if (out_size >= BSD + 2) k_scalar<<<1, 256>>>(out);
}